// round 15
// baseline (speedup 1.0000x reference)
#include <cuda_runtime.h>
#include <cuda_bf16.h>
#include <cstdint>

#define N_NODES 50000
#define N_EDGES 800000
#define IN_DIM  256
#define NCOLS   512
#define NBLK    49     // ceil(50000/1024)

// ---------------- scratch ----------------
__device__ unsigned short g_zb[N_NODES * 64];
__device__ unsigned short g_featb[(size_t)N_NODES * 256];
__device__ float4 g_el[N_NODES];
__device__ float4 g_er[N_NODES];
__device__ float4 g_xc[N_NODES];
__device__ float4 g_px[N_NODES];
__device__ int    g_deg[N_NODES];
__device__ int    g_off[N_NODES + 1];
__device__ int    g_cur[N_NODES];
__device__ int    g_srcs[N_EDGES];
__device__ int    g_bsum[NBLK];
__device__ int    g_boff[NBLK];
__device__ unsigned int g_elmax[4];
__device__ unsigned short g_wcat_hi[NCOLS * IN_DIM];
__device__ unsigned short g_wcat_lo[NCOLS * IN_DIM];

__device__ __forceinline__ float lrelu(float v) { return v > 0.f ? v : 0.2f * v; }
__device__ __forceinline__ float sel4(float4 v, int h) {
    float r = v.x;
    r = (h == 1) ? v.y : r;
    r = (h == 2) ? v.z : r;
    r = (h == 3) ? v.w : r;
    return r;
}
__device__ __forceinline__ float bflo(uint32_t u) { return __uint_as_float(u << 16); }
__device__ __forceinline__ float bfhi(uint32_t u) { return __uint_as_float(u & 0xFFFF0000u); }
__device__ __forceinline__ uint32_t packbf(float a, float b) {
    return (uint32_t)__bfloat16_as_ushort(__float2bfloat16(a)) |
           ((uint32_t)__bfloat16_as_ushort(__float2bfloat16(b)) << 16);
}
__device__ __forceinline__ uint32_t fenc(float f) {
    uint32_t b = __float_as_uint(f);
    return (b & 0x80000000u) ? ~b : (b | 0x80000000u);
}
__device__ __forceinline__ float fdec(uint32_t u) {
    uint32_t b = (u & 0x80000000u) ? (u ^ 0x80000000u) : ~u;
    return __uint_as_float(b);
}

__device__ __forceinline__ uint32_t smem_u32(const void* p) {
    uint32_t a;
    asm("{ .reg .u64 t; cvta.to.shared.u64 t, %1; cvt.u32.u64 %0, t; }" : "=r"(a) : "l"(p));
    return a;
}
__device__ __forceinline__ void ldsm4(uint32_t* r, uint32_t addr) {
    asm volatile("ldmatrix.sync.aligned.m8n8.x4.shared.b16 {%0,%1,%2,%3}, [%4];"
        : "=r"(r[0]), "=r"(r[1]), "=r"(r[2]), "=r"(r[3]) : "r"(addr));
}
__device__ __forceinline__ void mma16816(float* c, const uint32_t* a, const uint32_t* b) {
    asm volatile("mma.sync.aligned.m16n8k16.row.col.f32.bf16.bf16.f32 "
        "{%0,%1,%2,%3}, {%4,%5,%6,%7}, {%8,%9}, {%0,%1,%2,%3};"
        : "+f"(c[0]), "+f"(c[1]), "+f"(c[2]), "+f"(c[3])
        : "r"(a[0]), "r"(a[1]), "r"(a[2]), "r"(a[3]), "r"(b[0]), "r"(b[1]));
}
__device__ __forceinline__ void cpa16(uint32_t dst, const void* src, uint32_t sz) {
    asm volatile("cp.async.cg.shared.global [%0], [%1], 16, %2;"
        :: "r"(dst), "l"(src), "r"(sz) : "memory");
}
#define CPA_COMMIT() asm volatile("cp.async.commit_group;" ::: "memory")
#define CPA_WAIT1()  asm volatile("cp.async.wait_group 1;" ::: "memory")

// ---------------- CSR build ----------------
__global__ void k_zero_deg() {
    int i = blockIdx.x * blockDim.x + threadIdx.x;
    if (i < N_NODES) g_deg[i] = 0;
}
__global__ void k_hist(const int* __restrict__ dst) {
    int e = blockIdx.x * blockDim.x + threadIdx.x;
    if (e < N_EDGES) atomicAdd(&g_deg[dst[e]], 1);
}
__global__ __launch_bounds__(256) void k_bsum() {
    int b = blockIdx.x, t = threadIdx.x;
    int base = b * 1024 + t * 4;
    int s = 0;
    if (base + 4 <= N_NODES) {
        int4 d = *(const int4*)&g_deg[base];
        s = d.x + d.y + d.z + d.w;
    } else {
        #pragma unroll
        for (int q = 0; q < 4; q++)
            if (base + q < N_NODES) s += g_deg[base + q];
    }
    #pragma unroll
    for (int d = 16; d; d >>= 1) s += __shfl_xor_sync(0xffffffffu, s, d);
    __shared__ int ws[8];
    if ((t & 31) == 0) ws[t >> 5] = s;
    __syncthreads();
    if (t < 8) {
        int v = ws[t];
        #pragma unroll
        for (int d = 4; d; d >>= 1) v += __shfl_xor_sync(0xffu, v, d);
        if (t == 0) g_bsum[b] = v;
    }
}
__global__ void k_bscan() {
    __shared__ int buf[64];
    int t = threadIdx.x;
    int v = (t < NBLK) ? g_bsum[t] : 0;
    buf[t] = v;
    __syncthreads();
    #pragma unroll
    for (int off = 1; off < 64; off <<= 1) {
        int add = (t >= off) ? buf[t - off] : 0;
        __syncthreads();
        buf[t] += add;
        __syncthreads();
    }
    if (t < NBLK) g_boff[t] = buf[t] - v;
    if (t == NBLK - 1) g_off[N_NODES] = buf[t];
}
__global__ __launch_bounds__(256) void k_localscan() {
    int b = blockIdx.x, t = threadIdx.x, lane = t & 31, w = t >> 5;
    int base = b * 1024 + t * 4;
    int d0 = 0, d1 = 0, d2 = 0, d3 = 0;
    if (base + 4 <= N_NODES) {
        int4 d = *(const int4*)&g_deg[base];
        d0 = d.x; d1 = d.y; d2 = d.z; d3 = d.w;
    } else {
        if (base + 0 < N_NODES) d0 = g_deg[base + 0];
        if (base + 1 < N_NODES) d1 = g_deg[base + 1];
        if (base + 2 < N_NODES) d2 = g_deg[base + 2];
        if (base + 3 < N_NODES) d3 = g_deg[base + 3];
    }
    int s = d0 + d1 + d2 + d3;
    int v = s;
    #pragma unroll
    for (int off = 1; off < 32; off <<= 1) {
        int u = __shfl_up_sync(0xffffffffu, v, off);
        if (lane >= off) v += u;
    }
    __shared__ int wsum[8];
    if (lane == 31) wsum[w] = v;
    __syncthreads();
    if (t < 8) {
        int xv = wsum[t];
        #pragma unroll
        for (int off = 1; off < 8; off <<= 1) {
            int u = __shfl_up_sync(0xffu, xv, off);
            if (t >= off) xv += u;
        }
        wsum[t] = xv;
    }
    __syncthreads();
    int run = g_boff[b] + (w ? wsum[w - 1] : 0) + (v - s);
    if (base + 0 < N_NODES) { g_off[base + 0] = run; g_cur[base + 0] = run; } run += d0;
    if (base + 1 < N_NODES) { g_off[base + 1] = run; g_cur[base + 1] = run; } run += d1;
    if (base + 2 < N_NODES) { g_off[base + 2] = run; g_cur[base + 2] = run; } run += d2;
    if (base + 3 < N_NODES) { g_off[base + 3] = run; g_cur[base + 3] = run; }
}
__global__ void k_scatter(const int* __restrict__ src, const int* __restrict__ dst) {
    int e = blockIdx.x * blockDim.x + threadIdx.x;
    if (e < N_EDGES) {
        int p = atomicAdd(&g_cur[dst[e]], 1);
        g_srcs[p] = src[e];
    }
}

// ---------------- weight concat (+ elmax init) ----------------
__global__ void k_prep_w(const float* __restrict__ W_gat, const float* __restrict__ attn_l,
                         const float* __restrict__ attn_r, const float* __restrict__ gate_m_W,
                         const float* __restrict__ merge_W, const float* __restrict__ gate_fn_W)
{
    int n = blockIdx.x, k = threadIdx.x;
    if (n == 0 && k < 4) g_elmax[k] = fenc(-1e30f);
    float v = 0.f;
    if (n < 256)      v = W_gat[k * 256 + n];
    else if (n < 320) v = gate_m_W[k * 64 + (n - 256)];
    else if (n < 384) v = merge_W[k * 64 + (n - 320)];
    else if (n < 388) v = gate_fn_W[k * 4 + (n - 384)];
    else if (n < 392) v = gate_fn_W[(320 + k) * 4 + (n - 388)];
    else if (n < 396) {
        int h = n - 392; float s = 0.f;
        for (int o = 0; o < 64; o++) s += W_gat[k * 256 + h * 64 + o] * attn_l[h * 64 + o];
        v = s;
    } else if (n < 400) {
        int h = n - 396; float s = 0.f;
        for (int o = 0; o < 64; o++) s += W_gat[k * 256 + h * 64 + o] * attn_r[h * 64 + o];
        v = s;
    }
    __nv_bfloat16 hi = __float2bfloat16(v);
    g_wcat_hi[n * 256 + k] = __bfloat16_as_ushort(hi);
    g_wcat_lo[n * 256 + k] = __bfloat16_as_ushort(__float2bfloat16(v - __bfloat162float(hi)));
}

// ---------------- pipelined HMMA GEMM: 2 stages -> 2-3 CTAs/SM ----------------
#define STAGE 36864
#define GEMM_SMEM (2 * STAGE)

__global__ __launch_bounds__(256, 2) void k_gemm_mma(
    const float* __restrict__ x,
    const float* __restrict__ gate_m_b, const float* __restrict__ merge_b,
    float* __restrict__ out)
{
    extern __shared__ __align__(16) char sm[];
    uint32_t sb = smem_u32(sm);
    int tid = threadIdx.x, w = tid >> 5, lane = tid & 31;
    int r0 = blockIdx.x * 128;
    int nb = blockIdx.y * 256;
    const bool full = (blockIdx.y != 0);
    int wm = (w & 1) * 64, wn = (w >> 1) * 64;

    int arow = tid >> 1, akg = tid & 1;
    int agr = r0 + arow;
    bool aok = (agr < N_NODES);
    if (!aok) agr = 0;
    const float* xp = x + (size_t)agr * 256 + akg * 8;
    uint32_t adst = arow * 48 + akg * 16;

    auto ld_a = [&](int ch, float4& a0, float4& a1) {
        if (aok) {
            a0 = *(const float4*)(xp + ch * 16);
            a1 = *(const float4*)(xp + ch * 16 + 4);
        } else {
            a0 = make_float4(0.f, 0.f, 0.f, 0.f);
            a1 = a0;
        }
    };
    auto st_a = [&](uint32_t base, float4 a0, float4 a1) {
        uint4 hh;
        hh.x = packbf(a0.x, a0.y); hh.y = packbf(a0.z, a0.w);
        hh.z = packbf(a1.x, a1.y); hh.w = packbf(a1.z, a1.w);
        *(uint4*)(sm + (base - sb) + adst) = hh;
        if (full) {
            float h0 = bflo(hh.x), h1 = bfhi(hh.x), h2 = bflo(hh.y), h3 = bfhi(hh.y);
            float h4 = bflo(hh.z), h5 = bfhi(hh.z), h6 = bflo(hh.w), h7 = bfhi(hh.w);
            uint4 ll;
            ll.x = packbf(a0.x - h0, a0.y - h1); ll.y = packbf(a0.z - h2, a0.w - h3);
            ll.z = packbf(a1.x - h4, a1.y - h5); ll.w = packbf(a1.z - h6, a1.w - h7);
            *(uint4*)(sm + (base - sb) + 6144 + adst) = ll;
        }
    };
    auto load_w = [&](int ch, uint32_t base) {
        int k0 = ch * 16;
        #pragma unroll
        for (int i = 0; i < 2; i++) {
            int q = tid + i * 256;
            int row = q >> 1, kg = q & 1;
            uint32_t wsz = (full && row >= 160) ? 0u : 16u;
            uint32_t d = base + 12288 + row * 48 + kg * 16;
            cpa16(d, g_wcat_hi + (size_t)(nb + row) * 256 + k0 + kg * 8, wsz);
            if (full) cpa16(d + 12288, g_wcat_lo + (size_t)(nb + row) * 256 + k0 + kg * 8, wsz);
        }
    };

    float acc[4][8][4];
    #pragma unroll
    for (int a = 0; a < 4; a++)
        #pragma unroll
        for (int b = 0; b < 8; b++)
            #pragma unroll
            for (int c = 0; c < 4; c++) acc[a][b][c] = 0.f;

    // prologue: chunks 0,1
    #pragma unroll
    for (int p = 0; p < 2; p++) {
        float4 a0, a1;
        ld_a(p, a0, a1);
        st_a(sb + p * STAGE, a0, a1);
        load_w(p, sb + p * STAGE);
        CPA_COMMIT();
    }
    float4 ap0, ap1;
    ld_a(2, ap0, ap1);    // pending A for chunk 2

    for (int ch = 0; ch < 16; ch++) {
        CPA_WAIT1();          // chunk ch's group complete
        __syncthreads();

        uint32_t base = sb + (ch & 1) * STAGE;
        uint32_t aH[4][4], aL[4][4], bf[4][4];
        int ar = wm + (lane & 7) + ((lane & 8) ? 8 : 0);
        int ac = ((lane & 16) ? 16 : 0);
        #pragma unroll
        for (int mt = 0; mt < 4; mt++) {
            ldsm4(aH[mt], base + (ar + mt * 16) * 48 + ac);
            if (full) ldsm4(aL[mt], base + 6144 + (ar + mt * 16) * 48 + ac);
        }
        int br = wn + (lane & 7) + ((lane & 16) ? 8 : 0);
        int bc = ((lane & 8) ? 16 : 0);
        #pragma unroll
        for (int nt = 0; nt < 4; nt++)
            ldsm4(bf[nt], base + 12288 + (br + nt * 16) * 48 + bc);
        #pragma unroll
        for (int mt = 0; mt < 4; mt++)
            #pragma unroll
            for (int nt = 0; nt < 4; nt++) {
                mma16816(acc[mt][nt * 2],     aH[mt], &bf[nt][0]);
                mma16816(acc[mt][nt * 2 + 1], aH[mt], &bf[nt][2]);
            }
        if (full) {
            #pragma unroll
            for (int mt = 0; mt < 4; mt++)
                #pragma unroll
                for (int nt = 0; nt < 4; nt++) {
                    mma16816(acc[mt][nt * 2],     aL[mt], &bf[nt][0]);
                    mma16816(acc[mt][nt * 2 + 1], aL[mt], &bf[nt][2]);
                }
            #pragma unroll
            for (int nt = 0; nt < 4; nt++)
                ldsm4(bf[nt], base + 24576 + (br + nt * 16) * 48 + bc);
            #pragma unroll
            for (int mt = 0; mt < 4; mt++)
                #pragma unroll
                for (int nt = 0; nt < 4; nt++) {
                    mma16816(acc[mt][nt * 2],     aH[mt], &bf[nt][0]);
                    mma16816(acc[mt][nt * 2 + 1], aH[mt], &bf[nt][2]);
                }
        }

        __syncthreads();      // all warps done reading buffer (ch&1)
        if (ch + 2 < 16) {
            st_a(sb + (ch & 1) * STAGE, ap0, ap1);
            load_w(ch + 2, sb + (ch & 1) * STAGE);
            CPA_COMMIT();
            if (ch + 3 < 16) ld_a(ch + 3, ap0, ap1);
        } else {
            CPA_COMMIT();     // keep group count consistent for WAIT1
        }
    }

    // epilogue (+ fused el-max atomics)
    int gcbase = nb + wn;
    #pragma unroll
    for (int nt = 0; nt < 8; nt++) {
        int gc = gcbase + nt * 8 + 2 * (lane & 3);
        if (gc >= 400) continue;
        float b0 = 0.f, b1 = 0.f;
        if (gc >= 256 && gc < 320) { b0 = gate_m_b[gc - 256]; b1 = gate_m_b[gc - 255]; }
        else if (gc >= 320 && gc < 384) { b0 = merge_b[gc - 320]; b1 = merge_b[gc - 319]; }
        const bool isel = (gc == 392 || gc == 394);
        float elm0 = -1e30f, elm1 = -1e30f;
        #pragma unroll
        for (int mt = 0; mt < 4; mt++) {
            int row0 = r0 + wm + mt * 16 + (lane >> 2);
            #pragma unroll
            for (int h = 0; h < 2; h++) {
                int row = row0 + h * 8;
                if (row >= N_NODES) continue;
                float v0 = acc[mt][nt][h * 2] + b0;
                float v1 = acc[mt][nt][h * 2 + 1] + b1;
                if (gc < 256)
                    ((uint32_t*)g_featb)[(size_t)row * 128 + (gc >> 1)] = packbf(v0, v1);
                else if (gc < 320)
                    ((uint32_t*)g_zb)[row * 32 + ((gc - 256) >> 1)] = packbf(v0, v1);
                else if (gc < 384)
                    *(float2*)(out + (size_t)row * 64 + (gc - 320)) = make_float2(v0, v1);
                else {
                    int cc = gc - 384;
                    float* bp = cc < 4 ? (float*)g_xc : cc < 8 ? (float*)g_px
                              : cc < 12 ? (float*)g_el : (float*)g_er;
                    *(float2*)(bp + (size_t)row * 4 + (cc & 3)) = make_float2(v0, v1);
                    if (isel) { elm0 = fmaxf(elm0, v0); elm1 = fmaxf(elm1, v1); }
                }
            }
        }
        if (isel) {
            atomicMax(&g_elmax[gc - 392], fenc(elm0));
            atomicMax(&g_elmax[gc - 391], fenc(elm1));
        }
    }
}

// ---------------- fused aggregation + gate + merge2 (4 nodes per warp) ----------------
__global__ __launch_bounds__(256, 3) void k_agg(
    const float* __restrict__ gate_fn_W, const float* __restrict__ gate_fn_b,
    const float* __restrict__ W2, float* __restrict__ out)
{
    __shared__ float4 s_wm[64];
    __shared__ float  s_W2[64 * 64];
    __shared__ float  s_gat[8][64];
    __shared__ float4 s_gb;
    int tid = threadIdx.x;
    if (tid < 64) s_wm[tid] = ((const float4*)gate_fn_W)[256 + tid];
    if (tid == 64) s_gb = *(const float4*)gate_fn_b;
    #pragma unroll
    for (int i = 0; i < 16; i++) s_W2[tid + i * 256] = W2[tid + i * 256];
    __syncthreads();

    int lane = tid & 31, w = tid >> 5;
    const int h = lane >> 3;
    const float* elf = (const float*)g_el;
    const float* pxf = (const float*)g_px;
    const uint32_t* zb = (const uint32_t*)g_zb;
    const uint4* fb = (const uint4*)g_featb;
    float elmax_h = fdec(g_elmax[h]);

    for (int nn = 0; nn < 4; nn++) {
        int n = blockIdx.x * 32 + w * 4 + nn;
        if (n >= N_NODES) break;

        int beg = g_off[n], end = g_off[n + 1];
        int deg = end - beg;
        if (deg == 0) continue;

        float er_h = ((const float*)(g_er + n))[h];
        float m_h = lrelu(elmax_h + er_h);

        float facc[8];
        #pragma unroll
        for (int k = 0; k < 8; k++) facc[k] = 0.f;
        float sH = 0.f, pxs = 0.f;
        float mzx = -1e30f, mzy = -1e30f;

        int j = beg;
        for (; j + 8 <= end; j += 8) {
            int s[8];
            float el[8], p[8];
            uint32_t z[8];
            uint4 f[8];
            #pragma unroll
            for (int q = 0; q < 8; q++) s[q] = g_srcs[j + q];
            #pragma unroll
            for (int q = 0; q < 8; q++) {
                el[q] = elf[4 * s[q] + h];
                p[q]  = pxf[4 * s[q] + h];
                z[q]  = zb[s[q] * 32 + lane];
                f[q]  = fb[(size_t)s[q] * 32 + lane];
            }
            #pragma unroll
            for (int q = 0; q < 8; q++) {
                float ex = __expf(lrelu(el[q] + er_h) - m_h);
                sH += ex;
                pxs += p[q];
                mzx = fmaxf(mzx, bflo(z[q]));
                mzy = fmaxf(mzy, bfhi(z[q]));
                facc[0] = fmaf(bflo(f[q].x), ex, facc[0]);
                facc[1] = fmaf(bfhi(f[q].x), ex, facc[1]);
                facc[2] = fmaf(bflo(f[q].y), ex, facc[2]);
                facc[3] = fmaf(bfhi(f[q].y), ex, facc[3]);
                facc[4] = fmaf(bflo(f[q].z), ex, facc[4]);
                facc[5] = fmaf(bfhi(f[q].z), ex, facc[5]);
                facc[6] = fmaf(bflo(f[q].w), ex, facc[6]);
                facc[7] = fmaf(bfhi(f[q].w), ex, facc[7]);
            }
        }
        for (; j < end; j++) {
            int s = g_srcs[j];
            float ex = __expf(lrelu(elf[4 * s + h] + er_h) - m_h);
            sH += ex;
            pxs += pxf[4 * s + h];
            uint32_t zr = zb[s * 32 + lane];
            mzx = fmaxf(mzx, bflo(zr)); mzy = fmaxf(mzy, bfhi(zr));
            uint4 fv = fb[(size_t)s * 32 + lane];
            facc[0] = fmaf(bflo(fv.x), ex, facc[0]);
            facc[1] = fmaf(bfhi(fv.x), ex, facc[1]);
            facc[2] = fmaf(bflo(fv.y), ex, facc[2]);
            facc[3] = fmaf(bfhi(fv.y), ex, facc[3]);
            facc[4] = fmaf(bflo(fv.z), ex, facc[4]);
            facc[5] = fmaf(bfhi(fv.z), ex, facc[5]);
            facc[6] = fmaf(bflo(fv.w), ex, facc[6]);
            facc[7] = fmaf(bfhi(fv.w), ex, facc[7]);
        }

        float4 wA = s_wm[2 * lane], wB = s_wm[2 * lane + 1];
        float4 gl;
        gl.x = mzx * wA.x + mzy * wB.x;
        gl.y = mzx * wA.y + mzy * wB.y;
        gl.z = mzx * wA.z + mzy * wB.z;
        gl.w = mzx * wA.w + mzy * wB.w;
        #pragma unroll
        for (int d = 16; d; d >>= 1) {
            gl.x += __shfl_xor_sync(0xffffffffu, gl.x, d);
            gl.y += __shfl_xor_sync(0xffffffffu, gl.y, d);
            gl.z += __shfl_xor_sync(0xffffffffu, gl.z, d);
            gl.w += __shfl_xor_sync(0xffffffffu, gl.w, d);
        }
        float invdeg = 1.f / (float)deg;
        float t = sel4(g_xc[n], h) + pxs * invdeg + sel4(gl, h) + sel4(s_gb, h);
        float gate = 1.f / (1.f + __expf(-t));
        float c = gate / fmaxf(sH, 1e-16f);

        float r[8];
        #pragma unroll
        for (int k = 0; k < 8; k++) {
            float v = facc[k] * c;
            v += __shfl_xor_sync(0xffffffffu, v, 8);
            v += __shfl_xor_sync(0xffffffffu, v, 16);
            r[k] = v * 0.25f;
        }
        if (lane < 8) {
            #pragma unroll
            for (int k = 0; k < 8; k++) s_gat[w][8 * lane + k] = r[k];
        }
        __syncwarp();

        float o0 = 0.f, o1 = 0.f;
        #pragma unroll 4
        for (int k = 0; k < 64; k++) {
            float g = s_gat[w][k];
            float2 w2 = ((const float2*)s_W2)[k * 32 + lane];
            o0 = fmaf(g, w2.x, o0);
            o1 = fmaf(g, w2.y, o1);
        }
        float2* op = (float2*)(out + (size_t)n * 64) + lane;
        float2 o = *op;
        o.x += o0; o.y += o1;
        *op = o;
        __syncwarp();
    }
}

// ---------------- launch: fork-join overlap ----------------
extern "C" void kernel_launch(void* const* d_in, const int* in_sizes, int n_in,
                              void* d_out, int out_size)
{
    const float* x         = (const float*)d_in[0];
    const int*   src       = (const int*)d_in[1];
    const int*   dst       = (const int*)d_in[2];
    const float* W_gat     = (const float*)d_in[3];
    const float* attn_l    = (const float*)d_in[4];
    const float* attn_r    = (const float*)d_in[5];
    const float* gate_m_W  = (const float*)d_in[6];
    const float* gate_m_b  = (const float*)d_in[7];
    const float* gate_fn_W = (const float*)d_in[8];
    const float* gate_fn_b = (const float*)d_in[9];
    const float* merge_W   = (const float*)d_in[10];
    const float* merge_b   = (const float*)d_in[11];
    float* out = (float*)d_out;

    static cudaStream_t s_csr = nullptr;
    static cudaEvent_t  ev_fork = nullptr, ev_join = nullptr, ev_prep = nullptr;
    static bool init_done = false;
    if (!init_done) {
        cudaStreamCreateWithFlags(&s_csr, cudaStreamNonBlocking);
        cudaEventCreateWithFlags(&ev_fork, cudaEventDisableTiming);
        cudaEventCreateWithFlags(&ev_join, cudaEventDisableTiming);
        cudaEventCreateWithFlags(&ev_prep, cudaEventDisableTiming);
        cudaFuncSetAttribute(k_gemm_mma, cudaFuncAttributeMaxDynamicSharedMemorySize, GEMM_SMEM);
        init_done = true;
    }

    // fork: prep_w + CSR chain on side stream
    cudaEventRecord(ev_fork, 0);
    cudaStreamWaitEvent(s_csr, ev_fork, 0);
    k_prep_w<<<NCOLS, 256, 0, s_csr>>>(W_gat, attn_l, attn_r, gate_m_W, merge_W, gate_fn_W);
    cudaEventRecord(ev_prep, s_csr);
    k_zero_deg<<<(N_NODES + 255) / 256, 256, 0, s_csr>>>();
    k_hist<<<(N_EDGES + 255) / 256, 256, 0, s_csr>>>(dst);
    k_bsum<<<NBLK, 256, 0, s_csr>>>();
    k_bscan<<<1, 64, 0, s_csr>>>();
    k_localscan<<<NBLK, 256, 0, s_csr>>>();
    k_scatter<<<(N_EDGES + 255) / 256, 256, 0, s_csr>>>(src, dst);
    cudaEventRecord(ev_join, s_csr);

    // main stream: GEMM (2-stage, multi-CTA/SM)
    cudaStreamWaitEvent(0, ev_prep, 0);
    k_gemm_mma<<<dim3((N_NODES + 127) / 128, 2), 256, GEMM_SMEM>>>(x, gate_m_b, merge_b, out);

    // join, then aggregate
    cudaStreamWaitEvent(0, ev_join, 0);
    k_agg<<<(N_NODES + 31) / 32, 256>>>(gate_fn_W, gate_fn_b, merge_W + 256 * 64, out);
}

// round 16
// speedup vs baseline: 2.2252x; 2.2252x over previous
#include <cuda_runtime.h>
#include <cuda_bf16.h>
#include <cstdint>

#define N_NODES 50000
#define N_EDGES 800000
#define IN_DIM  256
#define NCOLS   512
#define NBLK    49     // ceil(50000/1024)

// ---------------- scratch ----------------
__device__ unsigned short g_zb[N_NODES * 64];
__device__ unsigned short g_featb[(size_t)N_NODES * 256];
__device__ float4 g_el[N_NODES];
__device__ float4 g_er[N_NODES];
__device__ float4 g_xc[N_NODES];
__device__ float4 g_px[N_NODES];
__device__ int    g_deg[N_NODES];
__device__ int    g_off[N_NODES + 1];
__device__ int    g_cur[N_NODES];
__device__ int    g_srcs[N_EDGES];
__device__ int    g_bsum[NBLK];
__device__ int    g_boff[NBLK];
__device__ unsigned int g_elmax[4];
__device__ unsigned short g_wcat_hi[NCOLS * IN_DIM];
__device__ unsigned short g_wcat_lo[NCOLS * IN_DIM];

__device__ __forceinline__ float lrelu(float v) { return v > 0.f ? v : 0.2f * v; }
__device__ __forceinline__ float sel4(float4 v, int h) {
    float r = v.x;
    r = (h == 1) ? v.y : r;
    r = (h == 2) ? v.z : r;
    r = (h == 3) ? v.w : r;
    return r;
}
__device__ __forceinline__ float bflo(uint32_t u) { return __uint_as_float(u << 16); }
__device__ __forceinline__ float bfhi(uint32_t u) { return __uint_as_float(u & 0xFFFF0000u); }
__device__ __forceinline__ uint32_t packbf(float a, float b) {
    return (uint32_t)__bfloat16_as_ushort(__float2bfloat16(a)) |
           ((uint32_t)__bfloat16_as_ushort(__float2bfloat16(b)) << 16);
}
__device__ __forceinline__ uint32_t fenc(float f) {
    uint32_t b = __float_as_uint(f);
    return (b & 0x80000000u) ? ~b : (b | 0x80000000u);
}
__device__ __forceinline__ float fdec(uint32_t u) {
    uint32_t b = (u & 0x80000000u) ? (u ^ 0x80000000u) : ~u;
    return __uint_as_float(b);
}

__device__ __forceinline__ uint32_t smem_u32(const void* p) {
    uint32_t a;
    asm("{ .reg .u64 t; cvta.to.shared.u64 t, %1; cvt.u32.u64 %0, t; }" : "=r"(a) : "l"(p));
    return a;
}
__device__ __forceinline__ void ldsm4(uint32_t* r, uint32_t addr) {
    asm volatile("ldmatrix.sync.aligned.m8n8.x4.shared.b16 {%0,%1,%2,%3}, [%4];"
        : "=r"(r[0]), "=r"(r[1]), "=r"(r[2]), "=r"(r[3]) : "r"(addr));
}
__device__ __forceinline__ void mma16816(float* c, const uint32_t* a, const uint32_t* b) {
    asm volatile("mma.sync.aligned.m16n8k16.row.col.f32.bf16.bf16.f32 "
        "{%0,%1,%2,%3}, {%4,%5,%6,%7}, {%8,%9}, {%0,%1,%2,%3};"
        : "+f"(c[0]), "+f"(c[1]), "+f"(c[2]), "+f"(c[3])
        : "r"(a[0]), "r"(a[1]), "r"(a[2]), "r"(a[3]), "r"(b[0]), "r"(b[1]));
}
__device__ __forceinline__ void cpa16(uint32_t dst, const void* src, uint32_t sz) {
    asm volatile("cp.async.cg.shared.global [%0], [%1], 16, %2;"
        :: "r"(dst), "l"(src), "r"(sz) : "memory");
}
#define CPA_COMMIT() asm volatile("cp.async.commit_group;" ::: "memory")
#define CPA_WAIT2()  asm volatile("cp.async.wait_group 2;" ::: "memory")

// ---------------- CSR build ----------------
__global__ void k_zero_deg() {
    int i = blockIdx.x * blockDim.x + threadIdx.x;
    if (i < N_NODES) g_deg[i] = 0;
}
__global__ void k_hist(const int* __restrict__ dst) {
    int e = blockIdx.x * blockDim.x + threadIdx.x;
    if (e < N_EDGES) atomicAdd(&g_deg[dst[e]], 1);
}
__global__ __launch_bounds__(256) void k_bsum() {
    int b = blockIdx.x, t = threadIdx.x;
    int base = b * 1024 + t * 4;
    int s = 0;
    if (base + 4 <= N_NODES) {
        int4 d = *(const int4*)&g_deg[base];
        s = d.x + d.y + d.z + d.w;
    } else {
        #pragma unroll
        for (int q = 0; q < 4; q++)
            if (base + q < N_NODES) s += g_deg[base + q];
    }
    #pragma unroll
    for (int d = 16; d; d >>= 1) s += __shfl_xor_sync(0xffffffffu, s, d);
    __shared__ int ws[8];
    if ((t & 31) == 0) ws[t >> 5] = s;
    __syncthreads();
    if (t < 8) {
        int v = ws[t];
        #pragma unroll
        for (int d = 4; d; d >>= 1) v += __shfl_xor_sync(0xffu, v, d);
        if (t == 0) g_bsum[b] = v;
    }
}
__global__ void k_bscan() {
    __shared__ int buf[64];
    int t = threadIdx.x;
    int v = (t < NBLK) ? g_bsum[t] : 0;
    buf[t] = v;
    __syncthreads();
    #pragma unroll
    for (int off = 1; off < 64; off <<= 1) {
        int add = (t >= off) ? buf[t - off] : 0;
        __syncthreads();
        buf[t] += add;
        __syncthreads();
    }
    if (t < NBLK) g_boff[t] = buf[t] - v;
    if (t == NBLK - 1) g_off[N_NODES] = buf[t];
}
__global__ __launch_bounds__(256) void k_localscan() {
    int b = blockIdx.x, t = threadIdx.x, lane = t & 31, w = t >> 5;
    int base = b * 1024 + t * 4;
    int d0 = 0, d1 = 0, d2 = 0, d3 = 0;
    if (base + 4 <= N_NODES) {
        int4 d = *(const int4*)&g_deg[base];
        d0 = d.x; d1 = d.y; d2 = d.z; d3 = d.w;
    } else {
        if (base + 0 < N_NODES) d0 = g_deg[base + 0];
        if (base + 1 < N_NODES) d1 = g_deg[base + 1];
        if (base + 2 < N_NODES) d2 = g_deg[base + 2];
        if (base + 3 < N_NODES) d3 = g_deg[base + 3];
    }
    int s = d0 + d1 + d2 + d3;
    int v = s;
    #pragma unroll
    for (int off = 1; off < 32; off <<= 1) {
        int u = __shfl_up_sync(0xffffffffu, v, off);
        if (lane >= off) v += u;
    }
    __shared__ int wsum[8];
    if (lane == 31) wsum[w] = v;
    __syncthreads();
    if (t < 8) {
        int xv = wsum[t];
        #pragma unroll
        for (int off = 1; off < 8; off <<= 1) {
            int u = __shfl_up_sync(0xffu, xv, off);
            if (t >= off) xv += u;
        }
        wsum[t] = xv;
    }
    __syncthreads();
    int run = g_boff[b] + (w ? wsum[w - 1] : 0) + (v - s);
    if (base + 0 < N_NODES) { g_off[base + 0] = run; g_cur[base + 0] = run; } run += d0;
    if (base + 1 < N_NODES) { g_off[base + 1] = run; g_cur[base + 1] = run; } run += d1;
    if (base + 2 < N_NODES) { g_off[base + 2] = run; g_cur[base + 2] = run; } run += d2;
    if (base + 3 < N_NODES) { g_off[base + 3] = run; g_cur[base + 3] = run; }
}
__global__ void k_scatter(const int* __restrict__ src, const int* __restrict__ dst) {
    int e = blockIdx.x * blockDim.x + threadIdx.x;
    if (e < N_EDGES) {
        int p = atomicAdd(&g_cur[dst[e]], 1);
        g_srcs[p] = src[e];
    }
}

// ---------------- weight concat (+ elmax init) ----------------
__global__ void k_prep_w(const float* __restrict__ W_gat, const float* __restrict__ attn_l,
                         const float* __restrict__ attn_r, const float* __restrict__ gate_m_W,
                         const float* __restrict__ merge_W, const float* __restrict__ gate_fn_W)
{
    int n = blockIdx.x, k = threadIdx.x;
    if (n == 0 && k < 4) g_elmax[k] = fenc(-1e30f);
    float v = 0.f;
    if (n < 256)      v = W_gat[k * 256 + n];
    else if (n < 320) v = gate_m_W[k * 64 + (n - 256)];
    else if (n < 384) v = merge_W[k * 64 + (n - 320)];
    else if (n < 388) v = gate_fn_W[k * 4 + (n - 384)];
    else if (n < 392) v = gate_fn_W[(320 + k) * 4 + (n - 388)];
    else if (n < 396) {
        int h = n - 392; float s = 0.f;
        for (int o = 0; o < 64; o++) s += W_gat[k * 256 + h * 64 + o] * attn_l[h * 64 + o];
        v = s;
    } else if (n < 400) {
        int h = n - 396; float s = 0.f;
        for (int o = 0; o < 64; o++) s += W_gat[k * 256 + h * 64 + o] * attn_r[h * 64 + o];
        v = s;
    }
    __nv_bfloat16 hi = __float2bfloat16(v);
    g_wcat_hi[n * 256 + k] = __bfloat16_as_ushort(hi);
    g_wcat_lo[n * 256 + k] = __bfloat16_as_ushort(__float2bfloat16(v - __bfloat162float(hi)));
}

// ---------------- pipelined HMMA GEMM, in-kernel fp32->bf16 A split (4-stage) ----------------
#define STAGE 36864
#define GEMM_SMEM (4 * STAGE)

__global__ __launch_bounds__(256, 1) void k_gemm_mma(
    const float* __restrict__ x,
    const float* __restrict__ gate_m_b, const float* __restrict__ merge_b,
    float* __restrict__ out)
{
    extern __shared__ __align__(16) char sm[];
    uint32_t sb = smem_u32(sm);
    int tid = threadIdx.x, w = tid >> 5, lane = tid & 31;
    int r0 = blockIdx.x * 128;
    int nb = blockIdx.y * 256;
    const bool full = (blockIdx.y != 0);
    int wm = (w & 1) * 64, wn = (w >> 1) * 64;

    int arow = tid >> 1, akg = tid & 1;
    int agr = r0 + arow;
    bool aok = (agr < N_NODES);
    if (!aok) agr = 0;
    const float* xp = x + (size_t)agr * 256 + akg * 8;
    uint32_t adst = arow * 48 + akg * 16;

    auto ld_a = [&](int ch, float4& a0, float4& a1) {
        if (aok) {
            a0 = *(const float4*)(xp + ch * 16);
            a1 = *(const float4*)(xp + ch * 16 + 4);
        } else {
            a0 = make_float4(0.f, 0.f, 0.f, 0.f);
            a1 = a0;
        }
    };
    auto st_a = [&](uint32_t base, float4 a0, float4 a1) {
        uint4 hh;
        hh.x = packbf(a0.x, a0.y); hh.y = packbf(a0.z, a0.w);
        hh.z = packbf(a1.x, a1.y); hh.w = packbf(a1.z, a1.w);
        *(uint4*)(sm + (base - sb) + adst) = hh;
        if (full) {
            float h0 = bflo(hh.x), h1 = bfhi(hh.x), h2 = bflo(hh.y), h3 = bfhi(hh.y);
            float h4 = bflo(hh.z), h5 = bfhi(hh.z), h6 = bflo(hh.w), h7 = bfhi(hh.w);
            uint4 ll;
            ll.x = packbf(a0.x - h0, a0.y - h1); ll.y = packbf(a0.z - h2, a0.w - h3);
            ll.z = packbf(a1.x - h4, a1.y - h5); ll.w = packbf(a1.z - h6, a1.w - h7);
            *(uint4*)(sm + (base - sb) + 6144 + adst) = ll;
        }
    };
    auto load_w = [&](int ch, uint32_t base) {
        int k0 = ch * 16;
        #pragma unroll
        for (int i = 0; i < 2; i++) {
            int q = tid + i * 256;
            int row = q >> 1, kg = q & 1;
            uint32_t wsz = (full && row >= 160) ? 0u : 16u;
            uint32_t d = base + 12288 + row * 48 + kg * 16;
            cpa16(d, g_wcat_hi + (size_t)(nb + row) * 256 + k0 + kg * 8, wsz);
            if (full) cpa16(d + 12288, g_wcat_lo + (size_t)(nb + row) * 256 + k0 + kg * 8, wsz);
        }
    };

    float acc[4][8][4];
    #pragma unroll
    for (int a = 0; a < 4; a++)
        #pragma unroll
        for (int b = 0; b < 8; b++)
            #pragma unroll
            for (int c = 0; c < 4; c++) acc[a][b][c] = 0.f;

    #pragma unroll
    for (int p = 0; p < 3; p++) {
        float4 a0, a1;
        ld_a(p, a0, a1);
        st_a(sb + p * STAGE, a0, a1);
        load_w(p, sb + p * STAGE);
        CPA_COMMIT();
    }
    float4 ap0, ap1;
    ld_a(3, ap0, ap1);

    for (int ch = 0; ch < 16; ch++) {
        CPA_WAIT2();
        __syncthreads();
        if (ch + 3 < 16) {
            st_a(sb + ((ch + 3) & 3) * STAGE, ap0, ap1);
            load_w(ch + 3, sb + ((ch + 3) & 3) * STAGE);
        }
        CPA_COMMIT();
        if (ch + 4 < 16) ld_a(ch + 4, ap0, ap1);

        uint32_t base = sb + (ch & 3) * STAGE;
        uint32_t aH[4][4], aL[4][4], bf[4][4];
        int ar = wm + (lane & 7) + ((lane & 8) ? 8 : 0);
        int ac = ((lane & 16) ? 16 : 0);
        #pragma unroll
        for (int mt = 0; mt < 4; mt++) {
            ldsm4(aH[mt], base + (ar + mt * 16) * 48 + ac);
            if (full) ldsm4(aL[mt], base + 6144 + (ar + mt * 16) * 48 + ac);
        }
        int br = wn + (lane & 7) + ((lane & 16) ? 8 : 0);
        int bc = ((lane & 8) ? 16 : 0);
        #pragma unroll
        for (int nt = 0; nt < 4; nt++)
            ldsm4(bf[nt], base + 12288 + (br + nt * 16) * 48 + bc);
        #pragma unroll
        for (int mt = 0; mt < 4; mt++)
            #pragma unroll
            for (int nt = 0; nt < 4; nt++) {
                mma16816(acc[mt][nt * 2],     aH[mt], &bf[nt][0]);
                mma16816(acc[mt][nt * 2 + 1], aH[mt], &bf[nt][2]);
            }
        if (full) {
            #pragma unroll
            for (int mt = 0; mt < 4; mt++)
                #pragma unroll
                for (int nt = 0; nt < 4; nt++) {
                    mma16816(acc[mt][nt * 2],     aL[mt], &bf[nt][0]);
                    mma16816(acc[mt][nt * 2 + 1], aL[mt], &bf[nt][2]);
                }
            #pragma unroll
            for (int nt = 0; nt < 4; nt++)
                ldsm4(bf[nt], base + 24576 + (br + nt * 16) * 48 + bc);
            #pragma unroll
            for (int mt = 0; mt < 4; mt++)
                #pragma unroll
                for (int nt = 0; nt < 4; nt++) {
                    mma16816(acc[mt][nt * 2],     aH[mt], &bf[nt][0]);
                    mma16816(acc[mt][nt * 2 + 1], aH[mt], &bf[nt][2]);
                }
        }
    }

    // epilogue (+ fused el-max atomics)
    int gcbase = nb + wn;
    #pragma unroll
    for (int nt = 0; nt < 8; nt++) {
        int gc = gcbase + nt * 8 + 2 * (lane & 3);
        if (gc >= 400) continue;
        float b0 = 0.f, b1 = 0.f;
        if (gc >= 256 && gc < 320) { b0 = gate_m_b[gc - 256]; b1 = gate_m_b[gc - 255]; }
        else if (gc >= 320 && gc < 384) { b0 = merge_b[gc - 320]; b1 = merge_b[gc - 319]; }
        const bool isel = (gc == 392 || gc == 394);
        float elm0 = -1e30f, elm1 = -1e30f;
        #pragma unroll
        for (int mt = 0; mt < 4; mt++) {
            int row0 = r0 + wm + mt * 16 + (lane >> 2);
            #pragma unroll
            for (int h = 0; h < 2; h++) {
                int row = row0 + h * 8;
                if (row >= N_NODES) continue;
                float v0 = acc[mt][nt][h * 2] + b0;
                float v1 = acc[mt][nt][h * 2 + 1] + b1;
                if (gc < 256)
                    ((uint32_t*)g_featb)[(size_t)row * 128 + (gc >> 1)] = packbf(v0, v1);
                else if (gc < 320)
                    ((uint32_t*)g_zb)[row * 32 + ((gc - 256) >> 1)] = packbf(v0, v1);
                else if (gc < 384)
                    *(float2*)(out + (size_t)row * 64 + (gc - 320)) = make_float2(v0, v1);
                else {
                    int cc = gc - 384;
                    float* bp = cc < 4 ? (float*)g_xc : cc < 8 ? (float*)g_px
                              : cc < 12 ? (float*)g_el : (float*)g_er;
                    *(float2*)(bp + (size_t)row * 4 + (cc & 3)) = make_float2(v0, v1);
                    if (isel) { elm0 = fmaxf(elm0, v0); elm1 = fmaxf(elm1, v1); }
                }
            }
        }
        if (isel) {
            atomicMax(&g_elmax[gc - 392], fenc(elm0));
            atomicMax(&g_elmax[gc - 391], fenc(elm1));
        }
    }
}

// ---------------- fused aggregation + gate + merge2 (4 nodes per warp) ----------------
__global__ __launch_bounds__(256, 3) void k_agg(
    const float* __restrict__ gate_fn_W, const float* __restrict__ gate_fn_b,
    const float* __restrict__ W2, float* __restrict__ out)
{
    __shared__ float4 s_wm[64];
    __shared__ float  s_W2[64 * 64];
    __shared__ float  s_gat[8][64];
    __shared__ float4 s_gb;
    int tid = threadIdx.x;
    if (tid < 64) s_wm[tid] = ((const float4*)gate_fn_W)[256 + tid];
    if (tid == 64) s_gb = *(const float4*)gate_fn_b;
    #pragma unroll
    for (int i = 0; i < 16; i++) s_W2[tid + i * 256] = W2[tid + i * 256];
    __syncthreads();

    int lane = tid & 31, w = tid >> 5;
    const int h = lane >> 3;
    const float* elf = (const float*)g_el;
    const float* pxf = (const float*)g_px;
    const uint32_t* zb = (const uint32_t*)g_zb;
    const uint4* fb = (const uint4*)g_featb;
    float elmax_h = fdec(g_elmax[h]);

    for (int nn = 0; nn < 4; nn++) {
        int n = blockIdx.x * 32 + w * 4 + nn;
        if (n >= N_NODES) break;

        int beg = g_off[n], end = g_off[n + 1];
        int deg = end - beg;
        if (deg == 0) continue;

        float er_h = ((const float*)(g_er + n))[h];
        float m_h = lrelu(elmax_h + er_h);

        float facc[8];
        #pragma unroll
        for (int k = 0; k < 8; k++) facc[k] = 0.f;
        float sH = 0.f, pxs = 0.f;
        float mzx = -1e30f, mzy = -1e30f;

        int j = beg;
        for (; j + 8 <= end; j += 8) {
            int s[8];
            float el[8], p[8];
            uint32_t z[8];
            uint4 f[8];
            #pragma unroll
            for (int q = 0; q < 8; q++) s[q] = g_srcs[j + q];
            #pragma unroll
            for (int q = 0; q < 8; q++) {
                el[q] = elf[4 * s[q] + h];
                p[q]  = pxf[4 * s[q] + h];
                z[q]  = zb[s[q] * 32 + lane];
                f[q]  = fb[(size_t)s[q] * 32 + lane];
            }
            #pragma unroll
            for (int q = 0; q < 8; q++) {
                float ex = __expf(lrelu(el[q] + er_h) - m_h);
                sH += ex;
                pxs += p[q];
                mzx = fmaxf(mzx, bflo(z[q]));
                mzy = fmaxf(mzy, bfhi(z[q]));
                facc[0] = fmaf(bflo(f[q].x), ex, facc[0]);
                facc[1] = fmaf(bfhi(f[q].x), ex, facc[1]);
                facc[2] = fmaf(bflo(f[q].y), ex, facc[2]);
                facc[3] = fmaf(bfhi(f[q].y), ex, facc[3]);
                facc[4] = fmaf(bflo(f[q].z), ex, facc[4]);
                facc[5] = fmaf(bfhi(f[q].z), ex, facc[5]);
                facc[6] = fmaf(bflo(f[q].w), ex, facc[6]);
                facc[7] = fmaf(bfhi(f[q].w), ex, facc[7]);
            }
        }
        for (; j < end; j++) {
            int s = g_srcs[j];
            float ex = __expf(lrelu(elf[4 * s + h] + er_h) - m_h);
            sH += ex;
            pxs += pxf[4 * s + h];
            uint32_t zr = zb[s * 32 + lane];
            mzx = fmaxf(mzx, bflo(zr)); mzy = fmaxf(mzy, bfhi(zr));
            uint4 fv = fb[(size_t)s * 32 + lane];
            facc[0] = fmaf(bflo(fv.x), ex, facc[0]);
            facc[1] = fmaf(bfhi(fv.x), ex, facc[1]);
            facc[2] = fmaf(bflo(fv.y), ex, facc[2]);
            facc[3] = fmaf(bfhi(fv.y), ex, facc[3]);
            facc[4] = fmaf(bflo(fv.z), ex, facc[4]);
            facc[5] = fmaf(bfhi(fv.z), ex, facc[5]);
            facc[6] = fmaf(bflo(fv.w), ex, facc[6]);
            facc[7] = fmaf(bfhi(fv.w), ex, facc[7]);
        }

        float4 wA = s_wm[2 * lane], wB = s_wm[2 * lane + 1];
        float4 gl;
        gl.x = mzx * wA.x + mzy * wB.x;
        gl.y = mzx * wA.y + mzy * wB.y;
        gl.z = mzx * wA.z + mzy * wB.z;
        gl.w = mzx * wA.w + mzy * wB.w;
        #pragma unroll
        for (int d = 16; d; d >>= 1) {
            gl.x += __shfl_xor_sync(0xffffffffu, gl.x, d);
            gl.y += __shfl_xor_sync(0xffffffffu, gl.y, d);
            gl.z += __shfl_xor_sync(0xffffffffu, gl.z, d);
            gl.w += __shfl_xor_sync(0xffffffffu, gl.w, d);
        }
        float invdeg = 1.f / (float)deg;
        float t = sel4(g_xc[n], h) + pxs * invdeg + sel4(gl, h) + sel4(s_gb, h);
        float gate = 1.f / (1.f + __expf(-t));
        float c = gate / fmaxf(sH, 1e-16f);

        float r[8];
        #pragma unroll
        for (int k = 0; k < 8; k++) {
            float v = facc[k] * c;
            v += __shfl_xor_sync(0xffffffffu, v, 8);
            v += __shfl_xor_sync(0xffffffffu, v, 16);
            r[k] = v * 0.25f;
        }
        if (lane < 8) {
            #pragma unroll
            for (int k = 0; k < 8; k++) s_gat[w][8 * lane + k] = r[k];
        }
        __syncwarp();

        float o0 = 0.f, o1 = 0.f;
        #pragma unroll 4
        for (int k = 0; k < 64; k++) {
            float g = s_gat[w][k];
            float2 w2 = ((const float2*)s_W2)[k * 32 + lane];
            o0 = fmaf(g, w2.x, o0);
            o1 = fmaf(g, w2.y, o1);
        }
        float2* op = (float2*)(out + (size_t)n * 64) + lane;
        float2 o = *op;
        o.x += o0; o.y += o1;
        *op = o;
        __syncwarp();
    }
}

// ---------------- launch: fork-join overlap ----------------
extern "C" void kernel_launch(void* const* d_in, const int* in_sizes, int n_in,
                              void* d_out, int out_size)
{
    const float* x         = (const float*)d_in[0];
    const int*   src       = (const int*)d_in[1];
    const int*   dst       = (const int*)d_in[2];
    const float* W_gat     = (const float*)d_in[3];
    const float* attn_l    = (const float*)d_in[4];
    const float* attn_r    = (const float*)d_in[5];
    const float* gate_m_W  = (const float*)d_in[6];
    const float* gate_m_b  = (const float*)d_in[7];
    const float* gate_fn_W = (const float*)d_in[8];
    const float* gate_fn_b = (const float*)d_in[9];
    const float* merge_W   = (const float*)d_in[10];
    const float* merge_b   = (const float*)d_in[11];
    float* out = (float*)d_out;

    static cudaStream_t s_csr = nullptr;
    static cudaEvent_t  ev_fork = nullptr, ev_join = nullptr, ev_prep = nullptr;
    static bool init_done = false;
    if (!init_done) {
        cudaStreamCreateWithFlags(&s_csr, cudaStreamNonBlocking);
        cudaEventCreateWithFlags(&ev_fork, cudaEventDisableTiming);
        cudaEventCreateWithFlags(&ev_join, cudaEventDisableTiming);
        cudaEventCreateWithFlags(&ev_prep, cudaEventDisableTiming);
        cudaFuncSetAttribute(k_gemm_mma, cudaFuncAttributeMaxDynamicSharedMemorySize, GEMM_SMEM);
        init_done = true;
    }

    // fork: prep_w + CSR chain on side stream
    cudaEventRecord(ev_fork, 0);
    cudaStreamWaitEvent(s_csr, ev_fork, 0);
    k_prep_w<<<NCOLS, 256, 0, s_csr>>>(W_gat, attn_l, attn_r, gate_m_W, merge_W, gate_fn_W);
    cudaEventRecord(ev_prep, s_csr);
    k_zero_deg<<<(N_NODES + 255) / 256, 256, 0, s_csr>>>();
    k_hist<<<(N_EDGES + 255) / 256, 256, 0, s_csr>>>(dst);
    k_bsum<<<NBLK, 256, 0, s_csr>>>();
    k_bscan<<<1, 64, 0, s_csr>>>();
    k_localscan<<<NBLK, 256, 0, s_csr>>>();
    k_scatter<<<(N_EDGES + 255) / 256, 256, 0, s_csr>>>(src, dst);
    cudaEventRecord(ev_join, s_csr);

    // main stream: GEMM (A split fused in-kernel; el-max fused in epilogue)
    cudaStreamWaitEvent(0, ev_prep, 0);
    k_gemm_mma<<<dim3((N_NODES + 127) / 128, 2), 256, GEMM_SMEM>>>(x, gate_m_b, merge_b, out);

    // join, then aggregate (4 nodes per warp for imbalance smoothing)
    cudaStreamWaitEvent(0, ev_join, 0);
    k_agg<<<(N_NODES + 31) / 32, 256>>>(gate_fn_W, gate_fn_b, merge_W + 256 * 64, out);
}

// round 17
// speedup vs baseline: 2.4074x; 1.0819x over previous
#include <cuda_runtime.h>
#include <cuda_bf16.h>
#include <cstdint>

#define N_NODES 50000
#define N_EDGES 800000
#define IN_DIM  256
#define NCOLS   512
#define NBLK    49     // ceil(50000/1024)

// ---------------- scratch ----------------
__device__ unsigned short g_zb[N_NODES * 64];
__device__ unsigned short g_featb[(size_t)N_NODES * 256];
__device__ float4 g_el[N_NODES];
__device__ float4 g_er[N_NODES];
__device__ float4 g_xc[N_NODES];
__device__ float4 g_px[N_NODES];
__device__ int    g_deg[N_NODES];
__device__ int    g_off[N_NODES + 1];
__device__ int    g_cur[N_NODES];
__device__ int    g_srcs[N_EDGES];
__device__ int    g_bsum[NBLK];
__device__ int    g_boff[NBLK];
__device__ unsigned int g_elmax[4];
__device__ unsigned short g_wcat_hi[NCOLS * IN_DIM];
__device__ unsigned short g_wcat_lo[NCOLS * IN_DIM];

__device__ __forceinline__ float lrelu(float v) { return v > 0.f ? v : 0.2f * v; }
__device__ __forceinline__ float sel4(float4 v, int h) {
    float r = v.x;
    r = (h == 1) ? v.y : r;
    r = (h == 2) ? v.z : r;
    r = (h == 3) ? v.w : r;
    return r;
}
__device__ __forceinline__ float bflo(uint32_t u) { return __uint_as_float(u << 16); }
__device__ __forceinline__ float bfhi(uint32_t u) { return __uint_as_float(u & 0xFFFF0000u); }
__device__ __forceinline__ uint32_t packbf(float a, float b) {
    return (uint32_t)__bfloat16_as_ushort(__float2bfloat16(a)) |
           ((uint32_t)__bfloat16_as_ushort(__float2bfloat16(b)) << 16);
}
__device__ __forceinline__ uint32_t fenc(float f) {
    uint32_t b = __float_as_uint(f);
    return (b & 0x80000000u) ? ~b : (b | 0x80000000u);
}
__device__ __forceinline__ float fdec(uint32_t u) {
    uint32_t b = (u & 0x80000000u) ? (u ^ 0x80000000u) : ~u;
    return __uint_as_float(b);
}

__device__ __forceinline__ uint32_t smem_u32(const void* p) {
    uint32_t a;
    asm("{ .reg .u64 t; cvta.to.shared.u64 t, %1; cvt.u32.u64 %0, t; }" : "=r"(a) : "l"(p));
    return a;
}
__device__ __forceinline__ void ldsm4(uint32_t* r, uint32_t addr) {
    asm volatile("ldmatrix.sync.aligned.m8n8.x4.shared.b16 {%0,%1,%2,%3}, [%4];"
        : "=r"(r[0]), "=r"(r[1]), "=r"(r[2]), "=r"(r[3]) : "r"(addr));
}
__device__ __forceinline__ void mma16816(float* c, const uint32_t* a, const uint32_t* b) {
    asm volatile("mma.sync.aligned.m16n8k16.row.col.f32.bf16.bf16.f32 "
        "{%0,%1,%2,%3}, {%4,%5,%6,%7}, {%8,%9}, {%0,%1,%2,%3};"
        : "+f"(c[0]), "+f"(c[1]), "+f"(c[2]), "+f"(c[3])
        : "r"(a[0]), "r"(a[1]), "r"(a[2]), "r"(a[3]), "r"(b[0]), "r"(b[1]));
}
__device__ __forceinline__ void cpa16(uint32_t dst, const void* src, uint32_t sz) {
    asm volatile("cp.async.cg.shared.global [%0], [%1], 16, %2;"
        :: "r"(dst), "l"(src), "r"(sz) : "memory");
}
#define CPA_COMMIT() asm volatile("cp.async.commit_group;" ::: "memory")
#define CPA_WAIT2()  asm volatile("cp.async.wait_group 2;" ::: "memory")

// ---------------- CSR build ----------------
__global__ void k_zero_deg() {
    int i = blockIdx.x * blockDim.x + threadIdx.x;
    if (i < N_NODES) g_deg[i] = 0;
}
__global__ void k_hist(const int* __restrict__ dst) {
    int e = blockIdx.x * blockDim.x + threadIdx.x;
    if (e < N_EDGES) atomicAdd(&g_deg[dst[e]], 1);
}
__global__ __launch_bounds__(256) void k_bsum() {
    int b = blockIdx.x, t = threadIdx.x;
    int base = b * 1024 + t * 4;
    int s = 0;
    if (base + 4 <= N_NODES) {
        int4 d = *(const int4*)&g_deg[base];
        s = d.x + d.y + d.z + d.w;
    } else {
        #pragma unroll
        for (int q = 0; q < 4; q++)
            if (base + q < N_NODES) s += g_deg[base + q];
    }
    #pragma unroll
    for (int d = 16; d; d >>= 1) s += __shfl_xor_sync(0xffffffffu, s, d);
    __shared__ int ws[8];
    if ((t & 31) == 0) ws[t >> 5] = s;
    __syncthreads();
    if (t < 8) {
        int v = ws[t];
        #pragma unroll
        for (int d = 4; d; d >>= 1) v += __shfl_xor_sync(0xffu, v, d);
        if (t == 0) g_bsum[b] = v;
    }
}
__global__ void k_bscan() {
    __shared__ int buf[64];
    int t = threadIdx.x;
    int v = (t < NBLK) ? g_bsum[t] : 0;
    buf[t] = v;
    __syncthreads();
    #pragma unroll
    for (int off = 1; off < 64; off <<= 1) {
        int add = (t >= off) ? buf[t - off] : 0;
        __syncthreads();
        buf[t] += add;
        __syncthreads();
    }
    if (t < NBLK) g_boff[t] = buf[t] - v;
    if (t == NBLK - 1) g_off[N_NODES] = buf[t];
}
__global__ __launch_bounds__(256) void k_localscan() {
    int b = blockIdx.x, t = threadIdx.x, lane = t & 31, w = t >> 5;
    int base = b * 1024 + t * 4;
    int d0 = 0, d1 = 0, d2 = 0, d3 = 0;
    if (base + 4 <= N_NODES) {
        int4 d = *(const int4*)&g_deg[base];
        d0 = d.x; d1 = d.y; d2 = d.z; d3 = d.w;
    } else {
        if (base + 0 < N_NODES) d0 = g_deg[base + 0];
        if (base + 1 < N_NODES) d1 = g_deg[base + 1];
        if (base + 2 < N_NODES) d2 = g_deg[base + 2];
        if (base + 3 < N_NODES) d3 = g_deg[base + 3];
    }
    int s = d0 + d1 + d2 + d3;
    int v = s;
    #pragma unroll
    for (int off = 1; off < 32; off <<= 1) {
        int u = __shfl_up_sync(0xffffffffu, v, off);
        if (lane >= off) v += u;
    }
    __shared__ int wsum[8];
    if (lane == 31) wsum[w] = v;
    __syncthreads();
    if (t < 8) {
        int xv = wsum[t];
        #pragma unroll
        for (int off = 1; off < 8; off <<= 1) {
            int u = __shfl_up_sync(0xffu, xv, off);
            if (t >= off) xv += u;
        }
        wsum[t] = xv;
    }
    __syncthreads();
    int run = g_boff[b] + (w ? wsum[w - 1] : 0) + (v - s);
    if (base + 0 < N_NODES) { g_off[base + 0] = run; g_cur[base + 0] = run; } run += d0;
    if (base + 1 < N_NODES) { g_off[base + 1] = run; g_cur[base + 1] = run; } run += d1;
    if (base + 2 < N_NODES) { g_off[base + 2] = run; g_cur[base + 2] = run; } run += d2;
    if (base + 3 < N_NODES) { g_off[base + 3] = run; g_cur[base + 3] = run; }
}
__global__ void k_scatter(const int* __restrict__ src, const int* __restrict__ dst) {
    int e = blockIdx.x * blockDim.x + threadIdx.x;
    if (e < N_EDGES) {
        int p = atomicAdd(&g_cur[dst[e]], 1);
        g_srcs[p] = src[e];
    }
}

// ---------------- weight concat (+ elmax init) ----------------
__global__ void k_prep_w(const float* __restrict__ W_gat, const float* __restrict__ attn_l,
                         const float* __restrict__ attn_r, const float* __restrict__ gate_m_W,
                         const float* __restrict__ merge_W, const float* __restrict__ gate_fn_W)
{
    int n = blockIdx.x, k = threadIdx.x;
    if (n == 0 && k < 4) g_elmax[k] = fenc(-1e30f);
    float v = 0.f;
    if (n < 256)      v = W_gat[k * 256 + n];
    else if (n < 320) v = gate_m_W[k * 64 + (n - 256)];
    else if (n < 384) v = merge_W[k * 64 + (n - 320)];
    else if (n < 388) v = gate_fn_W[k * 4 + (n - 384)];
    else if (n < 392) v = gate_fn_W[(320 + k) * 4 + (n - 388)];
    else if (n < 396) {
        int h = n - 392; float s = 0.f;
        for (int o = 0; o < 64; o++) s += W_gat[k * 256 + h * 64 + o] * attn_l[h * 64 + o];
        v = s;
    } else if (n < 400) {
        int h = n - 396; float s = 0.f;
        for (int o = 0; o < 64; o++) s += W_gat[k * 256 + h * 64 + o] * attn_r[h * 64 + o];
        v = s;
    }
    __nv_bfloat16 hi = __float2bfloat16(v);
    g_wcat_hi[n * 256 + k] = __bfloat16_as_ushort(hi);
    g_wcat_lo[n * 256 + k] = __bfloat16_as_ushort(__float2bfloat16(v - __bfloat162float(hi)));
}

// ---------------- pipelined HMMA GEMM: N=128/CTA, 4-stage, 2 CTAs/SM ----------------
// blockIdx.y: 0,1 = feat halves (1 term); 2 = z+merge (3 terms); 3 = extras (3 terms)
#define STAGE 24576
#define GEMM_SMEM (4 * STAGE)

__global__ __launch_bounds__(256, 2) void k_gemm_mma(
    const float* __restrict__ x,
    const float* __restrict__ gate_m_b, const float* __restrict__ merge_b,
    float* __restrict__ out)
{
    extern __shared__ __align__(16) char sm[];
    uint32_t sb = smem_u32(sm);
    int tid = threadIdx.x, w = tid >> 5, lane = tid & 31;
    int r0 = blockIdx.x * 128;
    int nb = blockIdx.y * 128;
    const bool full = (blockIdx.y >= 2);
    int wm = (w & 1) * 64, wn = (w >> 1) * 32;

    int arow = tid >> 1, akg = tid & 1;
    int agr = r0 + arow;
    bool aok = (agr < N_NODES);
    if (!aok) agr = 0;
    const float* xp = x + (size_t)agr * 256 + akg * 8;
    uint32_t adst = arow * 48 + akg * 16;

    auto ld_a = [&](int ch, float4& a0, float4& a1) {
        if (aok) {
            a0 = *(const float4*)(xp + ch * 16);
            a1 = *(const float4*)(xp + ch * 16 + 4);
        } else {
            a0 = make_float4(0.f, 0.f, 0.f, 0.f);
            a1 = a0;
        }
    };
    auto st_a = [&](uint32_t base, float4 a0, float4 a1) {
        uint4 hh;
        hh.x = packbf(a0.x, a0.y); hh.y = packbf(a0.z, a0.w);
        hh.z = packbf(a1.x, a1.y); hh.w = packbf(a1.z, a1.w);
        *(uint4*)(sm + (base - sb) + adst) = hh;
        if (full) {
            float h0 = bflo(hh.x), h1 = bfhi(hh.x), h2 = bflo(hh.y), h3 = bfhi(hh.y);
            float h4 = bflo(hh.z), h5 = bfhi(hh.z), h6 = bflo(hh.w), h7 = bfhi(hh.w);
            uint4 ll;
            ll.x = packbf(a0.x - h0, a0.y - h1); ll.y = packbf(a0.z - h2, a0.w - h3);
            ll.z = packbf(a1.x - h4, a1.y - h5); ll.w = packbf(a1.z - h6, a1.w - h7);
            *(uint4*)(sm + (base - sb) + 6144 + adst) = ll;
        }
    };
    auto load_w = [&](int ch, uint32_t base) {
        int k0 = ch * 16;
        int row = tid >> 1, kg = tid & 1;       // 128 rows x 2 kg = 256 tasks
        uint32_t wsz = ((nb + row) >= 400) ? 0u : 16u;   // zero-fill padding rows
        uint32_t d = base + 12288 + row * 48 + kg * 16;
        cpa16(d, g_wcat_hi + (size_t)(nb + row) * 256 + k0 + kg * 8, wsz);
        if (full) cpa16(d + 6144, g_wcat_lo + (size_t)(nb + row) * 256 + k0 + kg * 8, wsz);
    };

    float acc[4][4][4];
    #pragma unroll
    for (int a = 0; a < 4; a++)
        #pragma unroll
        for (int b = 0; b < 4; b++)
            #pragma unroll
            for (int c = 0; c < 4; c++) acc[a][b][c] = 0.f;

    #pragma unroll
    for (int p = 0; p < 3; p++) {
        float4 a0, a1;
        ld_a(p, a0, a1);
        st_a(sb + p * STAGE, a0, a1);
        load_w(p, sb + p * STAGE);
        CPA_COMMIT();
    }
    float4 ap0, ap1;
    ld_a(3, ap0, ap1);

    for (int ch = 0; ch < 16; ch++) {
        CPA_WAIT2();
        __syncthreads();
        if (ch + 3 < 16) {
            st_a(sb + ((ch + 3) & 3) * STAGE, ap0, ap1);
            load_w(ch + 3, sb + ((ch + 3) & 3) * STAGE);
        }
        CPA_COMMIT();
        if (ch + 4 < 16) ld_a(ch + 4, ap0, ap1);

        uint32_t base = sb + (ch & 3) * STAGE;
        uint32_t aH[4][4], aL[4][4], bf[2][4];
        int ar = wm + (lane & 7) + ((lane & 8) ? 8 : 0);
        int ac = ((lane & 16) ? 16 : 0);
        #pragma unroll
        for (int mt = 0; mt < 4; mt++) {
            ldsm4(aH[mt], base + (ar + mt * 16) * 48 + ac);
            if (full) ldsm4(aL[mt], base + 6144 + (ar + mt * 16) * 48 + ac);
        }
        int br = wn + (lane & 7) + ((lane & 16) ? 8 : 0);
        int bc = ((lane & 8) ? 16 : 0);
        #pragma unroll
        for (int nt = 0; nt < 2; nt++)
            ldsm4(bf[nt], base + 12288 + (br + nt * 16) * 48 + bc);
        #pragma unroll
        for (int mt = 0; mt < 4; mt++)
            #pragma unroll
            for (int nt = 0; nt < 2; nt++) {
                mma16816(acc[mt][nt * 2],     aH[mt], &bf[nt][0]);
                mma16816(acc[mt][nt * 2 + 1], aH[mt], &bf[nt][2]);
            }
        if (full) {
            #pragma unroll
            for (int mt = 0; mt < 4; mt++)
                #pragma unroll
                for (int nt = 0; nt < 2; nt++) {
                    mma16816(acc[mt][nt * 2],     aL[mt], &bf[nt][0]);
                    mma16816(acc[mt][nt * 2 + 1], aL[mt], &bf[nt][2]);
                }
            #pragma unroll
            for (int nt = 0; nt < 2; nt++)
                ldsm4(bf[nt], base + 18432 + (br + nt * 16) * 48 + bc);
            #pragma unroll
            for (int mt = 0; mt < 4; mt++)
                #pragma unroll
                for (int nt = 0; nt < 2; nt++) {
                    mma16816(acc[mt][nt * 2],     aH[mt], &bf[nt][0]);
                    mma16816(acc[mt][nt * 2 + 1], aH[mt], &bf[nt][2]);
                }
        }
    }

    // epilogue (+ fused el-max atomics)
    int gcbase = nb + wn;
    #pragma unroll
    for (int nt = 0; nt < 4; nt++) {
        int gc = gcbase + nt * 8 + 2 * (lane & 3);
        if (gc >= 400) continue;
        float b0 = 0.f, b1 = 0.f;
        if (gc >= 256 && gc < 320) { b0 = gate_m_b[gc - 256]; b1 = gate_m_b[gc - 255]; }
        else if (gc >= 320 && gc < 384) { b0 = merge_b[gc - 320]; b1 = merge_b[gc - 319]; }
        const bool isel = (gc == 392 || gc == 394);
        float elm0 = -1e30f, elm1 = -1e30f;
        #pragma unroll
        for (int mt = 0; mt < 4; mt++) {
            int row0 = r0 + wm + mt * 16 + (lane >> 2);
            #pragma unroll
            for (int h = 0; h < 2; h++) {
                int row = row0 + h * 8;
                if (row >= N_NODES) continue;
                float v0 = acc[mt][nt][h * 2] + b0;
                float v1 = acc[mt][nt][h * 2 + 1] + b1;
                if (gc < 256)
                    ((uint32_t*)g_featb)[(size_t)row * 128 + (gc >> 1)] = packbf(v0, v1);
                else if (gc < 320)
                    ((uint32_t*)g_zb)[row * 32 + ((gc - 256) >> 1)] = packbf(v0, v1);
                else if (gc < 384)
                    *(float2*)(out + (size_t)row * 64 + (gc - 320)) = make_float2(v0, v1);
                else {
                    int cc = gc - 384;
                    float* bp = cc < 4 ? (float*)g_xc : cc < 8 ? (float*)g_px
                              : cc < 12 ? (float*)g_el : (float*)g_er;
                    *(float2*)(bp + (size_t)row * 4 + (cc & 3)) = make_float2(v0, v1);
                    if (isel) { elm0 = fmaxf(elm0, v0); elm1 = fmaxf(elm1, v1); }
                }
            }
        }
        if (isel) {
            atomicMax(&g_elmax[gc - 392], fenc(elm0));
            atomicMax(&g_elmax[gc - 391], fenc(elm1));
        }
    }
}

// ---------------- fused aggregation + gate + merge2 (4 nodes per warp) ----------------
__global__ __launch_bounds__(256, 3) void k_agg(
    const float* __restrict__ gate_fn_W, const float* __restrict__ gate_fn_b,
    const float* __restrict__ W2, float* __restrict__ out)
{
    __shared__ float4 s_wm[64];
    __shared__ float  s_W2[64 * 64];
    __shared__ float  s_gat[8][64];
    __shared__ float4 s_gb;
    int tid = threadIdx.x;
    if (tid < 64) s_wm[tid] = ((const float4*)gate_fn_W)[256 + tid];
    if (tid == 64) s_gb = *(const float4*)gate_fn_b;
    #pragma unroll
    for (int i = 0; i < 16; i++) s_W2[tid + i * 256] = W2[tid + i * 256];
    __syncthreads();

    int lane = tid & 31, w = tid >> 5;
    const int h = lane >> 3;
    const float* elf = (const float*)g_el;
    const float* pxf = (const float*)g_px;
    const uint32_t* zb = (const uint32_t*)g_zb;
    const uint4* fb = (const uint4*)g_featb;
    float elmax_h = fdec(g_elmax[h]);

    for (int nn = 0; nn < 4; nn++) {
        int n = blockIdx.x * 32 + w * 4 + nn;
        if (n >= N_NODES) break;

        int beg = g_off[n], end = g_off[n + 1];
        int deg = end - beg;
        if (deg == 0) continue;

        float er_h = ((const float*)(g_er + n))[h];
        float m_h = lrelu(elmax_h + er_h);

        float facc[8];
        #pragma unroll
        for (int k = 0; k < 8; k++) facc[k] = 0.f;
        float sH = 0.f, pxs = 0.f;
        float mzx = -1e30f, mzy = -1e30f;

        int j = beg;
        for (; j + 8 <= end; j += 8) {
            int s[8];
            float el[8], p[8];
            uint32_t z[8];
            uint4 f[8];
            #pragma unroll
            for (int q = 0; q < 8; q++) s[q] = g_srcs[j + q];
            #pragma unroll
            for (int q = 0; q < 8; q++) {
                el[q] = elf[4 * s[q] + h];
                p[q]  = pxf[4 * s[q] + h];
                z[q]  = zb[s[q] * 32 + lane];
                f[q]  = fb[(size_t)s[q] * 32 + lane];
            }
            #pragma unroll
            for (int q = 0; q < 8; q++) {
                float ex = __expf(lrelu(el[q] + er_h) - m_h);
                sH += ex;
                pxs += p[q];
                mzx = fmaxf(mzx, bflo(z[q]));
                mzy = fmaxf(mzy, bfhi(z[q]));
                facc[0] = fmaf(bflo(f[q].x), ex, facc[0]);
                facc[1] = fmaf(bfhi(f[q].x), ex, facc[1]);
                facc[2] = fmaf(bflo(f[q].y), ex, facc[2]);
                facc[3] = fmaf(bfhi(f[q].y), ex, facc[3]);
                facc[4] = fmaf(bflo(f[q].z), ex, facc[4]);
                facc[5] = fmaf(bfhi(f[q].z), ex, facc[5]);
                facc[6] = fmaf(bflo(f[q].w), ex, facc[6]);
                facc[7] = fmaf(bfhi(f[q].w), ex, facc[7]);
            }
        }
        for (; j < end; j++) {
            int s = g_srcs[j];
            float ex = __expf(lrelu(elf[4 * s + h] + er_h) - m_h);
            sH += ex;
            pxs += pxf[4 * s + h];
            uint32_t zr = zb[s * 32 + lane];
            mzx = fmaxf(mzx, bflo(zr)); mzy = fmaxf(mzy, bfhi(zr));
            uint4 fv = fb[(size_t)s * 32 + lane];
            facc[0] = fmaf(bflo(fv.x), ex, facc[0]);
            facc[1] = fmaf(bfhi(fv.x), ex, facc[1]);
            facc[2] = fmaf(bflo(fv.y), ex, facc[2]);
            facc[3] = fmaf(bfhi(fv.y), ex, facc[3]);
            facc[4] = fmaf(bflo(fv.z), ex, facc[4]);
            facc[5] = fmaf(bfhi(fv.z), ex, facc[5]);
            facc[6] = fmaf(bflo(fv.w), ex, facc[6]);
            facc[7] = fmaf(bfhi(fv.w), ex, facc[7]);
        }

        float4 wA = s_wm[2 * lane], wB = s_wm[2 * lane + 1];
        float4 gl;
        gl.x = mzx * wA.x + mzy * wB.x;
        gl.y = mzx * wA.y + mzy * wB.y;
        gl.z = mzx * wA.z + mzy * wB.z;
        gl.w = mzx * wA.w + mzy * wB.w;
        #pragma unroll
        for (int d = 16; d; d >>= 1) {
            gl.x += __shfl_xor_sync(0xffffffffu, gl.x, d);
            gl.y += __shfl_xor_sync(0xffffffffu, gl.y, d);
            gl.z += __shfl_xor_sync(0xffffffffu, gl.z, d);
            gl.w += __shfl_xor_sync(0xffffffffu, gl.w, d);
        }
        float invdeg = 1.f / (float)deg;
        float t = sel4(g_xc[n], h) + pxs * invdeg + sel4(gl, h) + sel4(s_gb, h);
        float gate = 1.f / (1.f + __expf(-t));
        float c = gate / fmaxf(sH, 1e-16f);

        float r[8];
        #pragma unroll
        for (int k = 0; k < 8; k++) {
            float v = facc[k] * c;
            v += __shfl_xor_sync(0xffffffffu, v, 8);
            v += __shfl_xor_sync(0xffffffffu, v, 16);
            r[k] = v * 0.25f;
        }
        if (lane < 8) {
            #pragma unroll
            for (int k = 0; k < 8; k++) s_gat[w][8 * lane + k] = r[k];
        }
        __syncwarp();

        float o0 = 0.f, o1 = 0.f;
        #pragma unroll 4
        for (int k = 0; k < 64; k++) {
            float g = s_gat[w][k];
            float2 w2 = ((const float2*)s_W2)[k * 32 + lane];
            o0 = fmaf(g, w2.x, o0);
            o1 = fmaf(g, w2.y, o1);
        }
        float2* op = (float2*)(out + (size_t)n * 64) + lane;
        float2 o = *op;
        o.x += o0; o.y += o1;
        *op = o;
        __syncwarp();
    }
}

// ---------------- launch: fork-join overlap ----------------
extern "C" void kernel_launch(void* const* d_in, const int* in_sizes, int n_in,
                              void* d_out, int out_size)
{
    const float* x         = (const float*)d_in[0];
    const int*   src       = (const int*)d_in[1];
    const int*   dst       = (const int*)d_in[2];
    const float* W_gat     = (const float*)d_in[3];
    const float* attn_l    = (const float*)d_in[4];
    const float* attn_r    = (const float*)d_in[5];
    const float* gate_m_W  = (const float*)d_in[6];
    const float* gate_m_b  = (const float*)d_in[7];
    const float* gate_fn_W = (const float*)d_in[8];
    const float* gate_fn_b = (const float*)d_in[9];
    const float* merge_W   = (const float*)d_in[10];
    const float* merge_b   = (const float*)d_in[11];
    float* out = (float*)d_out;

    static cudaStream_t s_csr = nullptr;
    static cudaEvent_t  ev_fork = nullptr, ev_join = nullptr, ev_prep = nullptr;
    static bool init_done = false;
    if (!init_done) {
        cudaStreamCreateWithFlags(&s_csr, cudaStreamNonBlocking);
        cudaEventCreateWithFlags(&ev_fork, cudaEventDisableTiming);
        cudaEventCreateWithFlags(&ev_join, cudaEventDisableTiming);
        cudaEventCreateWithFlags(&ev_prep, cudaEventDisableTiming);
        cudaFuncSetAttribute(k_gemm_mma, cudaFuncAttributeMaxDynamicSharedMemorySize, GEMM_SMEM);
        init_done = true;
    }

    // fork: prep_w + CSR chain on side stream
    cudaEventRecord(ev_fork, 0);
    cudaStreamWaitEvent(s_csr, ev_fork, 0);
    k_prep_w<<<NCOLS, 256, 0, s_csr>>>(W_gat, attn_l, attn_r, gate_m_W, merge_W, gate_fn_W);
    cudaEventRecord(ev_prep, s_csr);
    k_zero_deg<<<(N_NODES + 255) / 256, 256, 0, s_csr>>>();
    k_hist<<<(N_EDGES + 255) / 256, 256, 0, s_csr>>>(dst);
    k_bsum<<<NBLK, 256, 0, s_csr>>>();
    k_bscan<<<1, 64, 0, s_csr>>>();
    k_localscan<<<NBLK, 256, 0, s_csr>>>();
    k_scatter<<<(N_EDGES + 255) / 256, 256, 0, s_csr>>>(src, dst);
    cudaEventRecord(ev_join, s_csr);

    // main stream: GEMM (N=128 tiles, 2 CTAs/SM)
    cudaStreamWaitEvent(0, ev_prep, 0);
    k_gemm_mma<<<dim3((N_NODES + 127) / 128, 4), 256, GEMM_SMEM>>>(x, gate_m_b, merge_b, out);

    // join, then aggregate
    cudaStreamWaitEvent(0, ev_join, 0);
    k_agg<<<(N_NODES + 31) / 32, 256>>>(gate_fn_W, gate_fn_b, merge_W + 256 * 64, out);
}